// round 2
// baseline (speedup 1.0000x reference)
#include <cuda_runtime.h>
#include <math.h>

#define BS   8192           // B*S
#define SEQ  1024
#define NB   8
#define NH   4
#define DMODEL 768
#define DV   192            // per-head V dim

// ---------------- scratch (static device memory; no allocations) -------------
__device__ float g_q[BS * 32];
__device__ float g_k[BS * 32];
__device__ float g_att[BS * DMODEL];
__device__ float g_pam[BS * DMODEL];
__device__ float g_posp[BS * DMODEL];

// ---------------- kernel 1: fused q/k projection + ReLU ----------------------
// one warp per row; lane = output column (32 cols each for q and k)
__global__ __launch_bounds__(256)
void qk_proj(const float* __restrict__ x,
             const float* __restrict__ Wq, const float* __restrict__ bq,
             const float* __restrict__ Wk, const float* __restrict__ bk,
             float* __restrict__ q, float* __restrict__ k)
{
    const int row  = (blockIdx.x * blockDim.x + threadIdx.x) >> 5;
    const int lane = threadIdx.x & 31;
    if (row >= BS) return;
    const float* xr = x + (size_t)row * DMODEL;
    float aq = bq[lane];
    float ak = bk[lane];
#pragma unroll 8
    for (int d = 0; d < DMODEL; ++d) {
        const float xv = __ldg(xr + d);
        aq = fmaf(xv, __ldg(Wq + d * 32 + lane), aq);
        ak = fmaf(xv, __ldg(Wk + d * 32 + lane), ak);
    }
    q[(size_t)row * 32 + lane] = fmaxf(aq, 0.f);
    k[(size_t)row * 32 + lane] = fmaxf(ak, 0.f);
}

// ---------------- kernel 2: flash attention (query-axis softmax, transposed) -
// out[j] = sum_i softmax_i( Q[j]·K[i] * scale , masked ) * V[i]
// Qg rows are the reference "k", Kg rows the reference "q" (transpose trick).
// grid: (S/64, H, B); 256 threads.
template<int DQK>
__global__ __launch_bounds__(256)
void flash_kernel(const float* __restrict__ Qg, const float* __restrict__ Kg,
                  int ldqk, const float* __restrict__ Vg,
                  const int* __restrict__ mask,
                  float* __restrict__ Og, float scale)
{
    constexpr int PQ = DQK + 1;          // odd pad -> conflict-light
    extern __shared__ float smem[];
    float* sQ = smem;                    // [64][PQ]
    float* sK = sQ + 64 * PQ;            // [64][PQ]
    float* sV = sK + 64 * PQ;            // [64][196]
    float* sS = sV + 64 * 196;           // [64][65]
    float* sM = sS + 64 * 65;            // [64]
    float* sL = sM + 64;                 // [64]
    float* sC = sL + 64;                 // [64]
    int*   sMi = (int*)(sC + 64);        // [64]
    int*   sMj = sMi + 64;               // [64]

    const int tid = threadIdx.x;
    const int qt = blockIdx.x, h = blockIdx.y, b = blockIdx.z;
    const int j0 = qt * 64;
    const long brow = (long)b * SEQ;

    // load Q tile (vectorized; DQK % 4 == 0 for both 8 and 192)
    {
        constexpr int VW = DQK / 4;
        for (int idx = tid; idx < 64 * VW; idx += 256) {
            const int r = idx / VW, d4 = idx - r * VW;
            const float4 v = *(const float4*)(Qg + (brow + j0 + r) * (size_t)ldqk
                                              + h * DQK + d4 * 4);
            float* dst = sQ + r * PQ + d4 * 4;
            dst[0] = v.x; dst[1] = v.y; dst[2] = v.z; dst[3] = v.w;
        }
    }
    if (tid < 64) {
        sMj[tid] = mask[brow + j0 + tid];
        sM[tid]  = -1e30f;
        sL[tid]  = 0.f;
    }

    // accumulation micro-tile: thread owns 4 query rows x 12 V cols
    const int ta = tid >> 4, tb = tid & 15;
    const int jb = ta * 4, db = tb * 12;
    float O[4][12];
#pragma unroll
    for (int r = 0; r < 4; ++r)
#pragma unroll
        for (int c = 0; c < 12; ++c) O[r][c] = 0.f;

    __syncthreads();

    for (int kt = 0; kt < 16; ++kt) {
        const int i0 = kt * 64;
        // load K tile
        {
            constexpr int VW = DQK / 4;
            for (int idx = tid; idx < 64 * VW; idx += 256) {
                const int r = idx / VW, d4 = idx - r * VW;
                const float4 v = *(const float4*)(Kg + (brow + i0 + r) * (size_t)ldqk
                                                  + h * DQK + d4 * 4);
                float* dst = sK + r * PQ + d4 * 4;
                dst[0] = v.x; dst[1] = v.y; dst[2] = v.z; dst[3] = v.w;
            }
        }
        // load V tile (x head slice), 192 wide, padded stride 196 (f4 aligned)
        for (int idx = tid; idx < 64 * 48; idx += 256) {
            const int r = idx / 48, d4 = idx - r * 48;
            const float4 v = *(const float4*)(Vg + (brow + i0 + r) * (size_t)DMODEL
                                              + h * DV + d4 * 4);
            *(float4*)(sV + r * 196 + d4 * 4) = v;
        }
        if (tid < 64) sMi[tid] = mask[brow + i0 + tid];
        __syncthreads();

        // ---- scores: S[j][i] = Q[j]·K[i], 4x4 micro-tile per thread ----
        {
            const int jj = (tid >> 4) * 4, ii = (tid & 15) * 4;
            float acc[4][4];
#pragma unroll
            for (int a = 0; a < 4; ++a)
#pragma unroll
                for (int c = 0; c < 4; ++c) acc[a][c] = 0.f;
#pragma unroll 4
            for (int d = 0; d < DQK; ++d) {
                float qv[4], kv[4];
#pragma unroll
                for (int a = 0; a < 4; ++a) qv[a] = sQ[(jj + a) * PQ + d];
#pragma unroll
                for (int c = 0; c < 4; ++c) kv[c] = sK[(ii + c) * PQ + d];
#pragma unroll
                for (int a = 0; a < 4; ++a)
#pragma unroll
                    for (int c = 0; c < 4; ++c)
                        acc[a][c] = fmaf(qv[a], kv[c], acc[a][c]);
            }
#pragma unroll
            for (int a = 0; a < 4; ++a)
#pragma unroll
                for (int c = 0; c < 4; ++c)
                    sS[(jj + a) * 65 + ii + c] = acc[a][c];
        }
        __syncthreads();

        // ---- online softmax over this key tile (4 lanes per query row) ----
        {
            const int j = tid >> 2, tc = tid & 3;
            const bool mj = (sMj[j] != 0);
            float vv[16];
            float mt = -1e30f;
#pragma unroll
            for (int t2 = 0; t2 < 16; ++t2) {
                const int i = tc * 16 + t2;
                const float s = (mj && sMi[i]) ? sS[j * 65 + i] * scale : -1e7f;
                vv[t2] = s;
                mt = fmaxf(mt, s);
            }
            mt = fmaxf(mt, __shfl_xor_sync(0xffffffffu, mt, 1));
            mt = fmaxf(mt, __shfl_xor_sync(0xffffffffu, mt, 2));
            const float mold = sM[j];
            const float mnew = fmaxf(mold, mt);
            float lsum = 0.f;
#pragma unroll
            for (int t2 = 0; t2 < 16; ++t2) {
                const float p = __expf(vv[t2] - mnew);
                sS[j * 65 + tc * 16 + t2] = p;
                lsum += p;
            }
            lsum += __shfl_xor_sync(0xffffffffu, lsum, 1);
            lsum += __shfl_xor_sync(0xffffffffu, lsum, 2);
            if (tc == 0) {
                const float corr = __expf(mold - mnew);
                sC[j] = corr;
                sM[j] = mnew;
                sL[j] = sL[j] * corr + lsum;
            }
        }
        __syncthreads();

        // ---- O += P^T V  (4x12 register tile per thread) ----
        {
            float cr[4];
#pragma unroll
            for (int r = 0; r < 4; ++r) cr[r] = sC[jb + r];
#pragma unroll
            for (int r = 0; r < 4; ++r)
#pragma unroll
                for (int c = 0; c < 12; ++c) O[r][c] *= cr[r];
#pragma unroll 2
            for (int i = 0; i < 64; ++i) {
                float p[4];
#pragma unroll
                for (int r = 0; r < 4; ++r) p[r] = sS[(jb + r) * 65 + i];
                const float* vr = sV + i * 196 + db;
                const float4 va = *(const float4*)(vr);
                const float4 vb = *(const float4*)(vr + 4);
                const float4 vc = *(const float4*)(vr + 8);
#pragma unroll
                for (int r = 0; r < 4; ++r) {
                    O[r][0]  = fmaf(p[r], va.x, O[r][0]);
                    O[r][1]  = fmaf(p[r], va.y, O[r][1]);
                    O[r][2]  = fmaf(p[r], va.z, O[r][2]);
                    O[r][3]  = fmaf(p[r], va.w, O[r][3]);
                    O[r][4]  = fmaf(p[r], vb.x, O[r][4]);
                    O[r][5]  = fmaf(p[r], vb.y, O[r][5]);
                    O[r][6]  = fmaf(p[r], vb.z, O[r][6]);
                    O[r][7]  = fmaf(p[r], vb.w, O[r][7]);
                    O[r][8]  = fmaf(p[r], vc.x, O[r][8]);
                    O[r][9]  = fmaf(p[r], vc.y, O[r][9]);
                    O[r][10] = fmaf(p[r], vc.z, O[r][10]);
                    O[r][11] = fmaf(p[r], vc.w, O[r][11]);
                }
            }
        }
        __syncthreads();
    }

    // ---- finalize: divide by l, write out ----
#pragma unroll
    for (int r = 0; r < 4; ++r) {
        const float inv = 1.f / sL[jb + r];
        float* op = Og + (brow + j0 + jb + r) * (size_t)DMODEL + h * DV + db;
        float4 o;
        o.x = O[r][0] * inv; o.y = O[r][1] * inv; o.z = O[r][2] * inv; o.w = O[r][3] * inv;
        *(float4*)(op) = o;
        o.x = O[r][4] * inv; o.y = O[r][5] * inv; o.z = O[r][6] * inv; o.w = O[r][7] * inv;
        *(float4*)(op + 4) = o;
        o.x = O[r][8] * inv; o.y = O[r][9] * inv; o.z = O[r][10] * inv; o.w = O[r][11] * inv;
        *(float4*)(op + 8) = o;
    }
}

// ---------------- kernel 3: dual-input GEMM + bias + ReLU --------------------
// C[M,768] = relu(A0 @ W0 + (A1 @ W1) + bias), K=768 per pass, M=8192.
// 64x64 block tile, 4x4 per thread, 256 threads.
__global__ __launch_bounds__(256)
void gemm_dual(const float* __restrict__ A0, const float* __restrict__ W0,
               const float* __restrict__ A1, const float* __restrict__ W1,
               const float* __restrict__ bias, float* __restrict__ C)
{
    __shared__ float sA[16][68];
    __shared__ float sB[16][64];
    const int tid = threadIdx.x;
    const int n0 = blockIdx.x * 64;
    const int m0 = blockIdx.y * 64;
    const int ty = tid >> 4, tx = tid & 15;
    const int lr = tid >> 2, lc = tid & 3;   // A loads
    const int wk = tid >> 4, wn = tid & 15;  // W loads

    float acc[4][4];
#pragma unroll
    for (int i = 0; i < 4; ++i)
#pragma unroll
        for (int j = 0; j < 4; ++j) acc[i][j] = 0.f;

    for (int pass = 0; pass < 2; ++pass) {
        const float* A = pass ? A1 : A0;
        const float* W = pass ? W1 : W0;
        if (A == nullptr) continue;
        for (int kc = 0; kc < 768; kc += 16) {
            const float4 av = *(const float4*)(A + (size_t)(m0 + lr) * 768 + kc + lc * 4);
            const float4 wv = *(const float4*)(W + (size_t)(kc + wk) * 768 + n0 + wn * 4);
            __syncthreads();
            sA[lc * 4 + 0][lr] = av.x;
            sA[lc * 4 + 1][lr] = av.y;
            sA[lc * 4 + 2][lr] = av.z;
            sA[lc * 4 + 3][lr] = av.w;
            *(float4*)&sB[wk][wn * 4] = wv;
            __syncthreads();
#pragma unroll
            for (int kk = 0; kk < 16; ++kk) {
                const float4 a  = *(const float4*)&sA[kk][ty * 4];
                const float4 bv = *(const float4*)&sB[kk][tx * 4];
                acc[0][0] = fmaf(a.x, bv.x, acc[0][0]);
                acc[0][1] = fmaf(a.x, bv.y, acc[0][1]);
                acc[0][2] = fmaf(a.x, bv.z, acc[0][2]);
                acc[0][3] = fmaf(a.x, bv.w, acc[0][3]);
                acc[1][0] = fmaf(a.y, bv.x, acc[1][0]);
                acc[1][1] = fmaf(a.y, bv.y, acc[1][1]);
                acc[1][2] = fmaf(a.y, bv.z, acc[1][2]);
                acc[1][3] = fmaf(a.y, bv.w, acc[1][3]);
                acc[2][0] = fmaf(a.z, bv.x, acc[2][0]);
                acc[2][1] = fmaf(a.z, bv.y, acc[2][1]);
                acc[2][2] = fmaf(a.z, bv.z, acc[2][2]);
                acc[2][3] = fmaf(a.z, bv.w, acc[2][3]);
                acc[3][0] = fmaf(a.w, bv.x, acc[3][0]);
                acc[3][1] = fmaf(a.w, bv.y, acc[3][1]);
                acc[3][2] = fmaf(a.w, bv.z, acc[3][2]);
                acc[3][3] = fmaf(a.w, bv.w, acc[3][3]);
            }
        }
    }

    const float4 bb = *(const float4*)(bias + n0 + tx * 4);
#pragma unroll
    for (int i = 0; i < 4; ++i) {
        const size_t row = (size_t)(m0 + ty * 4 + i);
        float4 o;
        o.x = fmaxf(acc[i][0] + bb.x, 0.f);
        o.y = fmaxf(acc[i][1] + bb.y, 0.f);
        o.z = fmaxf(acc[i][2] + bb.z, 0.f);
        o.w = fmaxf(acc[i][3] + bb.w, 0.f);
        *(float4*)(C + row * 768 + n0 + tx * 4) = o;
    }
}

// ---------------- launch ------------------------------------------------------
extern "C" void kernel_launch(void* const* d_in, const int* in_sizes, int n_in,
                              void* d_out, int out_size)
{
    const float* x    = (const float*)d_in[0];
    const int*   mask = (const int*)  d_in[1];
    const float* pos  = (const float*)d_in[2];
    const float* Wq   = (const float*)d_in[3];
    const float* bq   = (const float*)d_in[4];
    const float* Wk   = (const float*)d_in[5];
    const float* bk   = (const float*)d_in[6];
    const float* Wpam = (const float*)d_in[7];
    const float* bpam = (const float*)d_in[8];
    const float* Wm   = (const float*)d_in[9];
    const float* bm   = (const float*)d_in[10];
    float* out = (float*)d_out;

    float *gq, *gk, *gatt, *gpam, *gposp;
    cudaGetSymbolAddress((void**)&gq,    g_q);
    cudaGetSymbolAddress((void**)&gk,    g_k);
    cudaGetSymbolAddress((void**)&gatt,  g_att);
    cudaGetSymbolAddress((void**)&gpam,  g_pam);
    cudaGetSymbolAddress((void**)&gposp, g_posp);

    // dynamic smem: 64*(DQK+1)*2 + 64*196 + 64*65 + 192 + 128 floats
    const int smem8   = (64 * 9 * 2   + 64 * 196 + 64 * 65 + 192 + 128) * 4;  // 72,704 B
    const int smem192 = (64 * 193 * 2 + 64 * 196 + 64 * 65 + 192 + 128) * 4;  // 166,912 B
    cudaFuncSetAttribute(flash_kernel<8>,   cudaFuncAttributeMaxDynamicSharedMemorySize, smem8);
    cudaFuncSetAttribute(flash_kernel<192>, cudaFuncAttributeMaxDynamicSharedMemorySize, smem192);

    const float sc_sam = 1.f / powf(8.f,   0.25f);
    const float sc_pam = 1.f / powf(192.f, 0.25f);

    // 1) q/k projections (+ReLU)
    qk_proj<<<1024, 256>>>(x, Wq, bq, Wk, bk, gq, gk);

    // 2) SAM attention: out[j] = sum_i softmax_i(q_i·k_j) x_i  -> Qflash = k, Kflash = q
    flash_kernel<8><<<dim3(16, NH, NB), 256, smem8>>>(gk, gq, 32, x, mask, gatt, sc_sam);

    // 3) PAM attention: Q = K = position
    flash_kernel<192><<<dim3(16, NH, NB), 256, smem192>>>(pos, pos, DMODEL, x, mask, gpam, sc_pam);

    // 4) pos_proj = relu(pam_out @ Wpam + bpam)
    gemm_dual<<<dim3(12, 128), 256>>>(gpam, Wpam, nullptr, nullptr, bpam, gposp);

    // 5) out = relu(att @ Wm[0:768] + pos_proj @ Wm[768:1536] + bm)
    gemm_dual<<<dim3(12, 128), 256>>>(gatt, Wm, gposp, Wm + 768 * 768, bm, out);
}

// round 7
// speedup vs baseline: 1.2870x; 1.2870x over previous
#include <cuda_runtime.h>
#include <math.h>
#include <stdint.h>

#define BS   8192           // B*S
#define SEQ  1024
#define NB   8
#define NH   4
#define DMODEL 768
#define DV   192            // per-head V dim

// ---------------- scratch (static device memory; no allocations) -------------
__device__ float g_q[BS * 32];
__device__ float g_k[BS * 32];
__device__ float g_att[BS * DMODEL];
__device__ float g_pam[BS * DMODEL];
__device__ float g_posp[BS * DMODEL];
__device__ float g_wpt[DMODEL * DMODEL];        // Wpam^T  [N=768][K=768]
__device__ float g_wmt[DMODEL * 2 * DMODEL];    // Wm^T    [N=768][K=1536]

// ---------------- helpers ----------------------------------------------------
__device__ __forceinline__ uint32_t f2tf32(float f) {
    uint32_t r;
    asm("cvt.rna.tf32.f32 %0, %1;" : "=r"(r) : "f"(f));
    return r;
}
__device__ __forceinline__ void mma_tf32(float c[4], const uint32_t a[4],
                                         const uint32_t b[2]) {
    asm volatile("mma.sync.aligned.m16n8k8.row.col.f32.tf32.tf32.f32 "
                 "{%0,%1,%2,%3}, {%4,%5,%6,%7}, {%8,%9}, {%0,%1,%2,%3};"
                 : "+f"(c[0]), "+f"(c[1]), "+f"(c[2]), "+f"(c[3])
                 : "r"(a[0]), "r"(a[1]), "r"(a[2]), "r"(a[3]),
                   "r"(b[0]), "r"(b[1]));
}

// ---------------- kernel 0: weight transpose  W[K][N] -> WT[N][K] ------------
__global__ __launch_bounds__(256)
void transpose_k(const float* __restrict__ W, float* __restrict__ WT, int K, int N)
{
    __shared__ float t[32][33];
    const int k0 = blockIdx.y * 32, n0 = blockIdx.x * 32;
    const int tx = threadIdx.x & 31, ty = threadIdx.x >> 5;
#pragma unroll
    for (int r = ty; r < 32; r += 8)
        t[r][tx] = W[(size_t)(k0 + r) * N + n0 + tx];
    __syncthreads();
#pragma unroll
    for (int r = ty; r < 32; r += 8)
        WT[(size_t)(n0 + r) * K + k0 + tx] = t[tx][r];
}

// ---------------- kernel 1: fused q/k projection + ReLU ----------------------
__global__ __launch_bounds__(256)
void qk_proj(const float* __restrict__ x,
             const float* __restrict__ Wq, const float* __restrict__ bq,
             const float* __restrict__ Wk, const float* __restrict__ bk,
             float* __restrict__ q, float* __restrict__ k)
{
    const int row  = (blockIdx.x * blockDim.x + threadIdx.x) >> 5;
    const int lane = threadIdx.x & 31;
    if (row >= BS) return;
    const float* xr = x + (size_t)row * DMODEL;
    float aq = bq[lane];
    float ak = bk[lane];
#pragma unroll 8
    for (int d = 0; d < DMODEL; ++d) {
        const float xv = __ldg(xr + d);
        aq = fmaf(xv, __ldg(Wq + d * 32 + lane), aq);
        ak = fmaf(xv, __ldg(Wk + d * 32 + lane), ak);
    }
    q[(size_t)row * 32 + lane] = fmaxf(aq, 0.f);
    k[(size_t)row * 32 + lane] = fmaxf(ak, 0.f);
}

// ---------------- kernel 2: flash attention (query-axis softmax, transposed) -
template<int DQK>
__global__ __launch_bounds__(256)
void flash_kernel(const float* __restrict__ Qg, const float* __restrict__ Kg,
                  int ldqk, const float* __restrict__ Vg,
                  const int* __restrict__ mask,
                  float* __restrict__ Og, float scale)
{
    constexpr int PQ = DQK + 1;
    extern __shared__ float smem[];
    float* sQ = smem;
    float* sK = sQ + 64 * PQ;
    float* sV = sK + 64 * PQ;
    float* sS = sV + 64 * 196;
    float* sM = sS + 64 * 65;
    float* sL = sM + 64;
    float* sC = sL + 64;
    int*   sMi = (int*)(sC + 64);
    int*   sMj = sMi + 64;

    const int tid = threadIdx.x;
    const int qt = blockIdx.x, h = blockIdx.y, b = blockIdx.z;
    const int j0 = qt * 64;
    const long brow = (long)b * SEQ;

    {
        constexpr int VW = DQK / 4;
        for (int idx = tid; idx < 64 * VW; idx += 256) {
            const int r = idx / VW, d4 = idx - r * VW;
            const float4 v = *(const float4*)(Qg + (brow + j0 + r) * (size_t)ldqk
                                              + h * DQK + d4 * 4);
            float* dst = sQ + r * PQ + d4 * 4;
            dst[0] = v.x; dst[1] = v.y; dst[2] = v.z; dst[3] = v.w;
        }
    }
    if (tid < 64) {
        sMj[tid] = mask[brow + j0 + tid];
        sM[tid]  = -1e30f;
        sL[tid]  = 0.f;
    }

    const int ta = tid >> 4, tb = tid & 15;
    const int jb = ta * 4, db = tb * 12;
    float O[4][12];
#pragma unroll
    for (int r = 0; r < 4; ++r)
#pragma unroll
        for (int c = 0; c < 12; ++c) O[r][c] = 0.f;

    __syncthreads();

    for (int kt = 0; kt < 16; ++kt) {
        const int i0 = kt * 64;
        {
            constexpr int VW = DQK / 4;
            for (int idx = tid; idx < 64 * VW; idx += 256) {
                const int r = idx / VW, d4 = idx - r * VW;
                const float4 v = *(const float4*)(Kg + (brow + i0 + r) * (size_t)ldqk
                                                  + h * DQK + d4 * 4);
                float* dst = sK + r * PQ + d4 * 4;
                dst[0] = v.x; dst[1] = v.y; dst[2] = v.z; dst[3] = v.w;
            }
        }
        for (int idx = tid; idx < 64 * 48; idx += 256) {
            const int r = idx / 48, d4 = idx - r * 48;
            const float4 v = *(const float4*)(Vg + (brow + i0 + r) * (size_t)DMODEL
                                              + h * DV + d4 * 4);
            *(float4*)(sV + r * 196 + d4 * 4) = v;
        }
        if (tid < 64) sMi[tid] = mask[brow + i0 + tid];
        __syncthreads();

        {
            const int jj = (tid >> 4) * 4, ii = (tid & 15) * 4;
            float acc[4][4];
#pragma unroll
            for (int a = 0; a < 4; ++a)
#pragma unroll
                for (int c = 0; c < 4; ++c) acc[a][c] = 0.f;
#pragma unroll 4
            for (int d = 0; d < DQK; ++d) {
                float qv[4], kv[4];
#pragma unroll
                for (int a = 0; a < 4; ++a) qv[a] = sQ[(jj + a) * PQ + d];
#pragma unroll
                for (int c = 0; c < 4; ++c) kv[c] = sK[(ii + c) * PQ + d];
#pragma unroll
                for (int a = 0; a < 4; ++a)
#pragma unroll
                    for (int c = 0; c < 4; ++c)
                        acc[a][c] = fmaf(qv[a], kv[c], acc[a][c]);
            }
#pragma unroll
            for (int a = 0; a < 4; ++a)
#pragma unroll
                for (int c = 0; c < 4; ++c)
                    sS[(jj + a) * 65 + ii + c] = acc[a][c];
        }
        __syncthreads();

        {
            const int j = tid >> 2, tc = tid & 3;
            const bool mj = (sMj[j] != 0);
            float vv[16];
            float mt = -1e30f;
#pragma unroll
            for (int t2 = 0; t2 < 16; ++t2) {
                const int i = tc * 16 + t2;
                const float s = (mj && sMi[i]) ? sS[j * 65 + i] * scale : -1e7f;
                vv[t2] = s;
                mt = fmaxf(mt, s);
            }
            mt = fmaxf(mt, __shfl_xor_sync(0xffffffffu, mt, 1));
            mt = fmaxf(mt, __shfl_xor_sync(0xffffffffu, mt, 2));
            const float mold = sM[j];
            const float mnew = fmaxf(mold, mt);
            float lsum = 0.f;
#pragma unroll
            for (int t2 = 0; t2 < 16; ++t2) {
                const float p = __expf(vv[t2] - mnew);
                sS[j * 65 + tc * 16 + t2] = p;
                lsum += p;
            }
            lsum += __shfl_xor_sync(0xffffffffu, lsum, 1);
            lsum += __shfl_xor_sync(0xffffffffu, lsum, 2);
            if (tc == 0) {
                const float corr = __expf(mold - mnew);
                sC[j] = corr;
                sM[j] = mnew;
                sL[j] = sL[j] * corr + lsum;
            }
        }
        __syncthreads();

        {
            float cr[4];
#pragma unroll
            for (int r = 0; r < 4; ++r) cr[r] = sC[jb + r];
#pragma unroll
            for (int r = 0; r < 4; ++r)
#pragma unroll
                for (int c = 0; c < 12; ++c) O[r][c] *= cr[r];
#pragma unroll 2
            for (int i = 0; i < 64; ++i) {
                float p[4];
#pragma unroll
                for (int r = 0; r < 4; ++r) p[r] = sS[(jb + r) * 65 + i];
                const float* vr = sV + i * 196 + db;
                const float4 va = *(const float4*)(vr);
                const float4 vb = *(const float4*)(vr + 4);
                const float4 vc = *(const float4*)(vr + 8);
#pragma unroll
                for (int r = 0; r < 4; ++r) {
                    O[r][0]  = fmaf(p[r], va.x, O[r][0]);
                    O[r][1]  = fmaf(p[r], va.y, O[r][1]);
                    O[r][2]  = fmaf(p[r], va.z, O[r][2]);
                    O[r][3]  = fmaf(p[r], va.w, O[r][3]);
                    O[r][4]  = fmaf(p[r], vb.x, O[r][4]);
                    O[r][5]  = fmaf(p[r], vb.y, O[r][5]);
                    O[r][6]  = fmaf(p[r], vb.z, O[r][6]);
                    O[r][7]  = fmaf(p[r], vb.w, O[r][7]);
                    O[r][8]  = fmaf(p[r], vc.x, O[r][8]);
                    O[r][9]  = fmaf(p[r], vc.y, O[r][9]);
                    O[r][10] = fmaf(p[r], vc.z, O[r][10]);
                    O[r][11] = fmaf(p[r], vc.w, O[r][11]);
                }
            }
        }
        __syncthreads();
    }

#pragma unroll
    for (int r = 0; r < 4; ++r) {
        const float inv = 1.f / sL[jb + r];
        float* op = Og + (brow + j0 + jb + r) * (size_t)DMODEL + h * DV + db;
        float4 o;
        o.x = O[r][0] * inv; o.y = O[r][1] * inv; o.z = O[r][2] * inv; o.w = O[r][3] * inv;
        *(float4*)(op) = o;
        o.x = O[r][4] * inv; o.y = O[r][5] * inv; o.z = O[r][6] * inv; o.w = O[r][7] * inv;
        *(float4*)(op + 4) = o;
        o.x = O[r][8] * inv; o.y = O[r][9] * inv; o.z = O[r][10] * inv; o.w = O[r][11] * inv;
        *(float4*)(op + 8) = o;
    }
}

// ---------------- kernel 3: mma.sync tf32 GEMM + bias + ReLU -----------------
// C[m][n] = relu( sum_k A(k)[m][k] * WT[n][k] + bias[n] )
// A(k) = A0 for k<768 else A1 (K-concat). CTA tile 128x128, K-chunk 32.
// 8 warps in 4x2; warp tile 32x64 = 2x8 m16n8k8 tf32 fragments.
__global__ __launch_bounds__(256, 2)
void gemm_mma(const float* __restrict__ A0, const float* __restrict__ A1,
              const float* __restrict__ WT, int ldw, int nk,
              const float* __restrict__ bias, float* __restrict__ C)
{
    __shared__ uint32_t sA[128 * 36];   // [m][k], pad 4 -> conflict-free frags
    __shared__ uint32_t sB[128 * 36];   // [n][k], pad 4

    const int tid  = threadIdx.x;
    const int wid  = tid >> 5, lane = tid & 31;
    const int g    = lane >> 2, t = lane & 3;
    const int mw   = wid >> 1;          // 0..3  -> 32-row slice
    const int nw   = wid & 1;           // 0..1  -> 64-col slice
    const int n0   = blockIdx.x * 128;
    const int m0   = blockIdx.y * 128;

    float acc[2][8][4];
#pragma unroll
    for (int mt = 0; mt < 2; ++mt)
#pragma unroll
        for (int nt = 0; nt < 8; ++nt)
#pragma unroll
            for (int e = 0; e < 4; ++e) acc[mt][nt][e] = 0.f;

    for (int kc = 0; kc < nk; ++kc) {
        const int kb = kc * 32;
        const float* Ag = (kb < 768) ? (A0 + (size_t)m0 * 768 + kb)
                                     : (A1 + (size_t)m0 * 768 + (kb - 768));
        const float* Bg = WT + (size_t)n0 * ldw + kb;
        __syncthreads();
#pragma unroll
        for (int i = 0; i < 4; ++i) {
            const int idx = tid + i * 256;
            const int r = idx >> 3, c4 = idx & 7;
            const float4 va = *(const float4*)(Ag + (size_t)r * 768 + c4 * 4);
            uint4 ua;
            ua.x = f2tf32(va.x); ua.y = f2tf32(va.y);
            ua.z = f2tf32(va.z); ua.w = f2tf32(va.w);
            *(uint4*)(sA + r * 36 + c4 * 4) = ua;
            const float4 vb = *(const float4*)(Bg + (size_t)r * ldw + c4 * 4);
            uint4 ub;
            ub.x = f2tf32(vb.x); ub.y = f2tf32(vb.y);
            ub.z = f2tf32(vb.z); ub.w = f2tf32(vb.w);
            *(uint4*)(sB + r * 36 + c4 * 4) = ub;
        }
        __syncthreads();

#pragma unroll
        for (int kk = 0; kk < 32; kk += 8) {
            uint32_t a[2][4];
#pragma unroll
            for (int mt = 0; mt < 2; ++mt) {
                const int mb = mw * 32 + mt * 16;
                a[mt][0] = sA[(mb + g)     * 36 + kk + t];
                a[mt][1] = sA[(mb + g + 8) * 36 + kk + t];
                a[mt][2] = sA[(mb + g)     * 36 + kk + t + 4];
                a[mt][3] = sA[(mb + g + 8) * 36 + kk + t + 4];
            }
            uint32_t b[8][2];
#pragma unroll
            for (int nt = 0; nt < 8; ++nt) {
                const int cn = nw * 64 + nt * 8 + g;
                b[nt][0] = sB[cn * 36 + kk + t];
                b[nt][1] = sB[cn * 36 + kk + t + 4];
            }
#pragma unroll
            for (int mt = 0; mt < 2; ++mt)
#pragma unroll
                for (int nt = 0; nt < 8; ++nt)
                    mma_tf32(acc[mt][nt], a[mt], b[nt]);
        }
    }

    // epilogue: bias + ReLU, float2 stores
#pragma unroll
    for (int mt = 0; mt < 2; ++mt) {
        const int r0 = m0 + mw * 32 + mt * 16 + g;
#pragma unroll
        for (int nt = 0; nt < 8; ++nt) {
            const int col = n0 + nw * 64 + nt * 8 + 2 * t;
            const float b0 = bias[col], b1 = bias[col + 1];
            float2 o0, o1;
            o0.x = fmaxf(acc[mt][nt][0] + b0, 0.f);
            o0.y = fmaxf(acc[mt][nt][1] + b1, 0.f);
            o1.x = fmaxf(acc[mt][nt][2] + b0, 0.f);
            o1.y = fmaxf(acc[mt][nt][3] + b1, 0.f);
            *(float2*)(C + (size_t)r0 * 768 + col)       = o0;
            *(float2*)(C + (size_t)(r0 + 8) * 768 + col) = o1;
        }
    }
}

// ---------------- launch ------------------------------------------------------
extern "C" void kernel_launch(void* const* d_in, const int* in_sizes, int n_in,
                              void* d_out, int out_size)
{
    const float* x    = (const float*)d_in[0];
    const int*   mask = (const int*)  d_in[1];
    const float* pos  = (const float*)d_in[2];
    const float* Wq   = (const float*)d_in[3];
    const float* bq   = (const float*)d_in[4];
    const float* Wk   = (const float*)d_in[5];
    const float* bk   = (const float*)d_in[6];
    const float* Wpam = (const float*)d_in[7];
    const float* bpam = (const float*)d_in[8];
    const float* Wm   = (const float*)d_in[9];
    const float* bm   = (const float*)d_in[10];
    float* out = (float*)d_out;

    float *gq, *gk, *gatt, *gpam, *gposp, *gwpt, *gwmt;
    cudaGetSymbolAddress((void**)&gq,    g_q);
    cudaGetSymbolAddress((void**)&gk,    g_k);
    cudaGetSymbolAddress((void**)&gatt,  g_att);
    cudaGetSymbolAddress((void**)&gpam,  g_pam);
    cudaGetSymbolAddress((void**)&gposp, g_posp);
    cudaGetSymbolAddress((void**)&gwpt,  g_wpt);
    cudaGetSymbolAddress((void**)&gwmt,  g_wmt);

    const int smem8   = (64 * 9 * 2   + 64 * 196 + 64 * 65 + 192 + 128) * 4;
    const int smem192 = (64 * 193 * 2 + 64 * 196 + 64 * 65 + 192 + 128) * 4;
    cudaFuncSetAttribute(flash_kernel<8>,   cudaFuncAttributeMaxDynamicSharedMemorySize, smem8);
    cudaFuncSetAttribute(flash_kernel<192>, cudaFuncAttributeMaxDynamicSharedMemorySize, smem192);

    const float sc_sam = 1.f / powf(8.f,   0.25f);
    const float sc_pam = 1.f / powf(192.f, 0.25f);

    // 0) transpose weights to K-major (mma.sync row.col wants B k-contiguous)
    transpose_k<<<dim3(24, 24), 256>>>(Wpam, gwpt, 768, 768);
    transpose_k<<<dim3(24, 48), 256>>>(Wm,   gwmt, 1536, 768);

    // 1) q/k projections (+ReLU)
    qk_proj<<<1024, 256>>>(x, Wq, bq, Wk, bk, gq, gk);

    // 2) SAM attention (transposed-flash trick: Qflash = k, Kflash = q)
    flash_kernel<8><<<dim3(16, NH, NB), 256, smem8>>>(gk, gq, 32, x, mask, gatt, sc_sam);

    // 3) PAM attention: Q = K = position
    flash_kernel<192><<<dim3(16, NH, NB), 256, smem192>>>(pos, pos, DMODEL, x, mask, gpam, sc_pam);

    // 4) pos_proj = relu(pam_out @ Wpam + bpam)   [mma.sync tf32]
    gemm_mma<<<dim3(6, 64), 256>>>(gpam, nullptr, gwpt, 768, 24, bpam, gposp);

    // 5) out = relu(att @ Wm_top + pos_proj @ Wm_bot + bm)   [mma.sync tf32]
    gemm_mma<<<dim3(6, 64), 256>>>(gatt, gposp, gwmt, 1536, 48, bm, out);
}

// round 8
// speedup vs baseline: 2.0860x; 1.6208x over previous
#include <cuda_runtime.h>
#include <cuda_fp16.h>
#include <math.h>
#include <stdint.h>

#define BS   8192           // B*S
#define SEQ  1024
#define NB   8
#define NH   4
#define DMODEL 768
#define DV   192            // per-head V dim

// ---------------- scratch (static device memory; no allocations) -------------
__device__ float g_q[BS * 32];
__device__ float g_k[BS * 32];
__device__ float g_att[BS * DMODEL];
__device__ float g_pam[BS * DMODEL];
__device__ float g_posp[BS * DMODEL];
__device__ float g_wpt[DMODEL * DMODEL];        // Wpam^T  [N=768][K=768]
__device__ float g_wmt[DMODEL * 2 * DMODEL];    // Wm^T    [N=768][K=1536]

// ---------------- helpers ----------------------------------------------------
__device__ __forceinline__ uint32_t f2tf32(float f) {
    uint32_t r;
    asm("cvt.rna.tf32.f32 %0, %1;" : "=r"(r) : "f"(f));
    return r;
}
__device__ __forceinline__ void mma_tf32(float c[4], const uint32_t a[4],
                                         const uint32_t b[2]) {
    asm volatile("mma.sync.aligned.m16n8k8.row.col.f32.tf32.tf32.f32 "
                 "{%0,%1,%2,%3}, {%4,%5,%6,%7}, {%8,%9}, {%0,%1,%2,%3};"
                 : "+f"(c[0]), "+f"(c[1]), "+f"(c[2]), "+f"(c[3])
                 : "r"(a[0]), "r"(a[1]), "r"(a[2]), "r"(a[3]),
                   "r"(b[0]), "r"(b[1]));
}
__device__ __forceinline__ void mma_f16(float c[4],
                                        uint32_t a0, uint32_t a1,
                                        uint32_t a2, uint32_t a3,
                                        uint32_t b0, uint32_t b1) {
    asm volatile("mma.sync.aligned.m16n8k16.row.col.f32.f16.f16.f32 "
                 "{%0,%1,%2,%3}, {%4,%5,%6,%7}, {%8,%9}, {%0,%1,%2,%3};"
                 : "+f"(c[0]), "+f"(c[1]), "+f"(c[2]), "+f"(c[3])
                 : "r"(a0), "r"(a1), "r"(a2), "r"(a3), "r"(b0), "r"(b1));
}
__device__ __forceinline__ uint32_t pack2h(float a, float b) {
    __half ha = __float2half_rn(a), hb = __float2half_rn(b);
    return (uint32_t)__half_as_ushort(ha) | ((uint32_t)__half_as_ushort(hb) << 16);
}
__device__ __forceinline__ void split2(float a, float b,
                                       uint32_t& hi, uint32_t& lo) {
    __half ha = __float2half_rn(a), hb = __float2half_rn(b);
    hi = (uint32_t)__half_as_ushort(ha) | ((uint32_t)__half_as_ushort(hb) << 16);
    float ra = a - __half2float(ha), rb = b - __half2float(hb);
    __half la = __float2half_rn(ra), lb = __float2half_rn(rb);
    lo = (uint32_t)__half_as_ushort(la) | ((uint32_t)__half_as_ushort(lb) << 16);
}

// ---------------- kernel 0: weight transpose  W[K][N] -> WT[N][K] ------------
__global__ __launch_bounds__(256)
void transpose_k(const float* __restrict__ W, float* __restrict__ WT, int K, int N)
{
    __shared__ float t[32][33];
    const int k0 = blockIdx.y * 32, n0 = blockIdx.x * 32;
    const int tx = threadIdx.x & 31, ty = threadIdx.x >> 5;
#pragma unroll
    for (int r = ty; r < 32; r += 8)
        t[r][tx] = W[(size_t)(k0 + r) * N + n0 + tx];
    __syncthreads();
#pragma unroll
    for (int r = ty; r < 32; r += 8)
        WT[(size_t)(n0 + r) * K + k0 + tx] = t[tx][r];
}

// ---------------- kernel 1: fused q/k projection + ReLU ----------------------
__global__ __launch_bounds__(256)
void qk_proj(const float* __restrict__ x,
             const float* __restrict__ Wq, const float* __restrict__ bq,
             const float* __restrict__ Wk, const float* __restrict__ bk,
             float* __restrict__ q, float* __restrict__ k)
{
    const int row  = (blockIdx.x * blockDim.x + threadIdx.x) >> 5;
    const int lane = threadIdx.x & 31;
    if (row >= BS) return;
    const float* xr = x + (size_t)row * DMODEL;
    float aq = bq[lane];
    float ak = bk[lane];
#pragma unroll 8
    for (int d = 0; d < DMODEL; ++d) {
        const float xv = __ldg(xr + d);
        aq = fmaf(xv, __ldg(Wq + d * 32 + lane), aq);
        ak = fmaf(xv, __ldg(Wk + d * 32 + lane), ak);
    }
    q[(size_t)row * 32 + lane] = fmaxf(aq, 0.f);
    k[(size_t)row * 32 + lane] = fmaxf(ak, 0.f);
}

// ---------------- kernel 2: mma-based flash attention -------------------------
// out[j] = sum_i softmax_i( Q[j]·K[i]*scale, masked ) * V[i]   (transpose trick)
// 64q x 64k tiles, 8 warps: (mw = wid>>1) 16-row slice, (nw = wid&1) half of i/d.
// QK^T: fp16 (2-term split when DQK=192). PV: fp16 single. Accum fp32.
template<int DQK>
__global__ __launch_bounds__(256)
void flash_mma(const float* __restrict__ Qg, const float* __restrict__ Kg,
               int ldqk, const float* __restrict__ Vg,
               const int* __restrict__ mask,
               float* __restrict__ Og, float scale)
{
    constexpr bool SPLIT = (DQK > 16);
    constexpr int NC  = (DQK + 15) / 16;   // k16 chunks for QK^T
    constexpr int LDQ = SPLIT ? 100 : 36;  // u32 row stride (= 4 mod 32)
    constexpr int QW  = DQK / 4;           // float4 groups per row
    // u32 offsets in dynamic smem
    constexpr int OQH = 0;
    constexpr int OQL = OQH + 64 * LDQ;
    constexpr int OKH = OQL + (SPLIT ? 64 * LDQ : 0);
    constexpr int OKL = OKH + 64 * LDQ;
    constexpr int OVT = OKL + (SPLIT ? 64 * LDQ : 0);
    constexpr int OP  = OVT + 192 * 36;
    constexpr int OMX = OP  + 64 * 36;
    constexpr int OLX = OMX + 64;
    constexpr int OCX = OLX + 64;
    constexpr int ORM = OCX + 64;
    constexpr int ORS = ORM + 128;
    constexpr int OMI = ORS + 128;
    constexpr int OMJ = OMI + 64;

    extern __shared__ __align__(16) uint32_t sm[];
    float* fsm = (float*)sm;
    int*   ism = (int*)sm;

    const int tid = threadIdx.x;
    const int wid = tid >> 5, lane = tid & 31;
    const int g = lane >> 2, t = lane & 3;
    const int mw = wid >> 1, nw = wid & 1;
    const int r0 = mw * 16 + g, r1 = r0 + 8;
    const int qt = blockIdx.x, h = blockIdx.y, b = blockIdx.z;
    const int j0 = qt * 64;
    const long brow = (long)b * SEQ;

    // zero the padded k-region for DQK=8 (cols 4..7 used by k16 frag upper half)
    if (!SPLIT) {
        for (int idx = tid; idx < 64 * 8; idx += 256) {
            sm[OQH + (idx >> 3) * LDQ + (idx & 7)] = 0;
            sm[OKH + (idx >> 3) * LDQ + (idx & 7)] = 0;
        }
    }
    // load Q tile once
    for (int idx = tid; idx < 64 * QW; idx += 256) {
        const int r = idx / QW, c4 = idx % QW;
        const float4 v = *(const float4*)(Qg + (brow + j0 + r) * (size_t)ldqk
                                          + h * DQK + c4 * 4);
        if (SPLIT) {
            uint32_t h01, l01, h23, l23;
            split2(v.x, v.y, h01, l01);
            split2(v.z, v.w, h23, l23);
            sm[OQH + r * LDQ + c4 * 2]     = h01;
            sm[OQH + r * LDQ + c4 * 2 + 1] = h23;
            sm[OQL + r * LDQ + c4 * 2]     = l01;
            sm[OQL + r * LDQ + c4 * 2 + 1] = l23;
        } else {
            sm[OQH + r * LDQ + c4 * 2]     = pack2h(v.x, v.y);
            sm[OQH + r * LDQ + c4 * 2 + 1] = pack2h(v.z, v.w);
        }
    }
    if (tid < 64) {
        ism[OMJ + tid] = mask[brow + j0 + tid];
        fsm[OMX + tid] = -1e30f;
        fsm[OLX + tid] = 0.f;
    }

    float acc[12][4];
#pragma unroll
    for (int n2 = 0; n2 < 12; ++n2)
#pragma unroll
        for (int e = 0; e < 4; ++e) acc[n2][e] = 0.f;

    for (int kt = 0; kt < 16; ++kt) {
        const int i0 = kt * 64;
        __syncthreads();   // prev PV done; safe to overwrite K/V/P tiles
        // ---- load K tile (fp16 / split-fp16) ----
        for (int idx = tid; idx < 64 * QW; idx += 256) {
            const int r = idx / QW, c4 = idx % QW;
            const float4 v = *(const float4*)(Kg + (brow + i0 + r) * (size_t)ldqk
                                              + h * DQK + c4 * 4);
            if (SPLIT) {
                uint32_t h01, l01, h23, l23;
                split2(v.x, v.y, h01, l01);
                split2(v.z, v.w, h23, l23);
                sm[OKH + r * LDQ + c4 * 2]     = h01;
                sm[OKH + r * LDQ + c4 * 2 + 1] = h23;
                sm[OKL + r * LDQ + c4 * 2]     = l01;
                sm[OKL + r * LDQ + c4 * 2 + 1] = l23;
            } else {
                sm[OKH + r * LDQ + c4 * 2]     = pack2h(v.x, v.y);
                sm[OKH + r * LDQ + c4 * 2 + 1] = pack2h(v.z, v.w);
            }
        }
        // ---- load V tile transposed: sVt[d][m] = half2(V[2m][d], V[2m+1][d]) ----
        for (int idx = tid; idx < 32 * 48; idx += 256) {
            const int d4 = idx >> 5, m = idx & 31;
            const float* vp = Vg + (brow + i0 + 2 * m) * (size_t)DMODEL
                              + h * DV + d4 * 4;
            const float4 a = *(const float4*)vp;
            const float4 c = *(const float4*)(vp + DMODEL);
            sm[OVT + (d4 * 4 + 0) * 36 + m] = pack2h(a.x, c.x);
            sm[OVT + (d4 * 4 + 1) * 36 + m] = pack2h(a.y, c.y);
            sm[OVT + (d4 * 4 + 2) * 36 + m] = pack2h(a.z, c.z);
            sm[OVT + (d4 * 4 + 3) * 36 + m] = pack2h(a.w, c.w);
        }
        if (tid < 64) ism[OMI + tid] = mask[brow + i0 + tid];
        __syncthreads();

        // ---- S = Q K^T via fp16 mma (split for DQK=192) ----
        float s[4][4];
#pragma unroll
        for (int nt = 0; nt < 4; ++nt)
#pragma unroll
            for (int e = 0; e < 4; ++e) s[nt][e] = 0.f;
#pragma unroll
        for (int ck = 0; ck < NC; ++ck) {
            const uint32_t ah0 = sm[OQH + r0 * LDQ + ck * 8 + t];
            const uint32_t ah1 = sm[OQH + r1 * LDQ + ck * 8 + t];
            const uint32_t ah2 = sm[OQH + r0 * LDQ + ck * 8 + t + 4];
            const uint32_t ah3 = sm[OQH + r1 * LDQ + ck * 8 + t + 4];
            uint32_t al0 = 0, al1 = 0, al2 = 0, al3 = 0;
            if (SPLIT) {
                al0 = sm[OQL + r0 * LDQ + ck * 8 + t];
                al1 = sm[OQL + r1 * LDQ + ck * 8 + t];
                al2 = sm[OQL + r0 * LDQ + ck * 8 + t + 4];
                al3 = sm[OQL + r1 * LDQ + ck * 8 + t + 4];
            }
#pragma unroll
            for (int nt = 0; nt < 4; ++nt) {
                const int iw = nw * 32 + nt * 8 + g;
                const uint32_t bh0 = sm[OKH + iw * LDQ + ck * 8 + t];
                const uint32_t bh1 = sm[OKH + iw * LDQ + ck * 8 + t + 4];
                mma_f16(s[nt], ah0, ah1, ah2, ah3, bh0, bh1);
                if (SPLIT) {
                    const uint32_t bl0 = sm[OKL + iw * LDQ + ck * 8 + t];
                    const uint32_t bl1 = sm[OKL + iw * LDQ + ck * 8 + t + 4];
                    mma_f16(s[nt], ah0, ah1, ah2, ah3, bl0, bl1);   // hi*lo
                    mma_f16(s[nt], al0, al1, al2, al3, bh0, bh1);   // lo*hi
                }
            }
        }

        // ---- mask + scale, row max ----
        const int mj0 = ism[OMJ + r0], mj1 = ism[OMJ + r1];
        float vv[4][4];
        float m0 = -1e30f, m1 = -1e30f;
#pragma unroll
        for (int nt = 0; nt < 4; ++nt) {
            const int ii = nw * 32 + nt * 8 + 2 * t;
            const int mi0 = ism[OMI + ii], mi1 = ism[OMI + ii + 1];
            vv[nt][0] = (mj0 && mi0) ? s[nt][0] * scale : -1e7f;
            vv[nt][1] = (mj0 && mi1) ? s[nt][1] * scale : -1e7f;
            vv[nt][2] = (mj1 && mi0) ? s[nt][2] * scale : -1e7f;
            vv[nt][3] = (mj1 && mi1) ? s[nt][3] * scale : -1e7f;
            m0 = fmaxf(m0, fmaxf(vv[nt][0], vv[nt][1]));
            m1 = fmaxf(m1, fmaxf(vv[nt][2], vv[nt][3]));
        }
        m0 = fmaxf(m0, __shfl_xor_sync(0xffffffffu, m0, 1));
        m0 = fmaxf(m0, __shfl_xor_sync(0xffffffffu, m0, 2));
        m1 = fmaxf(m1, __shfl_xor_sync(0xffffffffu, m1, 1));
        m1 = fmaxf(m1, __shfl_xor_sync(0xffffffffu, m1, 2));
        if (t == 0) {
            fsm[ORM + nw * 64 + r0] = m0;
            fsm[ORM + nw * 64 + r1] = m1;
        }
        __syncthreads();
        if (tid < 64) {
            const float mt = fmaxf(fsm[ORM + tid], fsm[ORM + 64 + tid]);
            const float mo = fsm[OMX + tid];
            const float mn = fmaxf(mo, mt);
            fsm[OCX + tid] = __expf(mo - mn);
            fsm[OMX + tid] = mn;
        }
        __syncthreads();

        // ---- p = exp(v - m), pack to half2, partial row sums ----
        const float mn0 = fsm[OMX + r0], mn1 = fsm[OMX + r1];
        float l0 = 0.f, l1 = 0.f;
#pragma unroll
        for (int nt = 0; nt < 4; ++nt) {
            const float p00 = __expf(vv[nt][0] - mn0);
            const float p01 = __expf(vv[nt][1] - mn0);
            const float p10 = __expf(vv[nt][2] - mn1);
            const float p11 = __expf(vv[nt][3] - mn1);
            l0 += p00 + p01;
            l1 += p10 + p11;
            sm[OP + r0 * 36 + nw * 16 + nt * 4 + t] = pack2h(p00, p01);
            sm[OP + r1 * 36 + nw * 16 + nt * 4 + t] = pack2h(p10, p11);
        }
        l0 += __shfl_xor_sync(0xffffffffu, l0, 1);
        l0 += __shfl_xor_sync(0xffffffffu, l0, 2);
        l1 += __shfl_xor_sync(0xffffffffu, l1, 1);
        l1 += __shfl_xor_sync(0xffffffffu, l1, 2);
        if (t == 0) {
            fsm[ORS + nw * 64 + r0] = l0;
            fsm[ORS + nw * 64 + r1] = l1;
        }
        __syncthreads();
        if (tid < 64)
            fsm[OLX + tid] = fsm[OLX + tid] * fsm[OCX + tid]
                             + fsm[ORS + tid] + fsm[ORS + 64 + tid];

        // ---- O = O*corr + P V  (fp16 mma over i) ----
        const float c0f = fsm[OCX + r0], c1f = fsm[OCX + r1];
#pragma unroll
        for (int n2 = 0; n2 < 12; ++n2) {
            acc[n2][0] *= c0f; acc[n2][1] *= c0f;
            acc[n2][2] *= c1f; acc[n2][3] *= c1f;
        }
#pragma unroll
        for (int ck = 0; ck < 4; ++ck) {
            const uint32_t pa0 = sm[OP + r0 * 36 + ck * 8 + t];
            const uint32_t pa1 = sm[OP + r1 * 36 + ck * 8 + t];
            const uint32_t pa2 = sm[OP + r0 * 36 + ck * 8 + t + 4];
            const uint32_t pa3 = sm[OP + r1 * 36 + ck * 8 + t + 4];
#pragma unroll
            for (int n2 = 0; n2 < 12; ++n2) {
                const int d0 = nw * 96 + n2 * 8 + g;
                const uint32_t b0 = sm[OVT + d0 * 36 + ck * 8 + t];
                const uint32_t b1 = sm[OVT + d0 * 36 + ck * 8 + t + 4];
                mma_f16(acc[n2], pa0, pa1, pa2, pa3, b0, b1);
            }
        }
    }
    __syncthreads();   // last sLx update must land

    // ---- epilogue: divide by l, write out ----
    const float inv0 = 1.f / fsm[OLX + r0];
    const float inv1 = 1.f / fsm[OLX + r1];
#pragma unroll
    for (int n2 = 0; n2 < 12; ++n2) {
        const int col = nw * 96 + n2 * 8 + 2 * t;
        float2 o0, o1;
        o0.x = acc[n2][0] * inv0; o0.y = acc[n2][1] * inv0;
        o1.x = acc[n2][2] * inv1; o1.y = acc[n2][3] * inv1;
        *(float2*)(Og + (brow + j0 + r0) * (size_t)DMODEL + h * DV + col) = o0;
        *(float2*)(Og + (brow + j0 + r1) * (size_t)DMODEL + h * DV + col) = o1;
    }
}

// smem sizes (u32) mirrored on host
static int flash_smem_bytes(int dqk) {
    const bool split = dqk > 16;
    const int ldq = split ? 100 : 36;
    int u = 64 * ldq;                 // QH
    if (split) u += 64 * ldq;         // QL
    u += 64 * ldq;                    // KH
    if (split) u += 64 * ldq;         // KL
    u += 192 * 36;                    // VT
    u += 64 * 36;                     // P
    u += 64 * 3 + 128 * 2 + 64 * 2;   // MX,LX,CX,RM,RS,MI,MJ
    return u * 4;
}

// ---------------- kernel 3: mma.sync tf32 GEMM + bias + ReLU -----------------
__global__ __launch_bounds__(256, 2)
void gemm_mma(const float* __restrict__ A0, const float* __restrict__ A1,
              const float* __restrict__ WT, int ldw, int nk,
              const float* __restrict__ bias, float* __restrict__ C)
{
    __shared__ uint32_t sA[128 * 36];
    __shared__ uint32_t sB[128 * 36];

    const int tid  = threadIdx.x;
    const int wid  = tid >> 5, lane = tid & 31;
    const int g    = lane >> 2, t = lane & 3;
    const int mw   = wid >> 1;
    const int nw   = wid & 1;
    const int n0   = blockIdx.x * 128;
    const int m0   = blockIdx.y * 128;

    float acc[2][8][4];
#pragma unroll
    for (int mt = 0; mt < 2; ++mt)
#pragma unroll
        for (int nt = 0; nt < 8; ++nt)
#pragma unroll
            for (int e = 0; e < 4; ++e) acc[mt][nt][e] = 0.f;

    for (int kc = 0; kc < nk; ++kc) {
        const int kb = kc * 32;
        const float* Ag = (kb < 768) ? (A0 + (size_t)m0 * 768 + kb)
                                     : (A1 + (size_t)m0 * 768 + (kb - 768));
        const float* Bg = WT + (size_t)n0 * ldw + kb;
        __syncthreads();
#pragma unroll
        for (int i = 0; i < 4; ++i) {
            const int idx = tid + i * 256;
            const int r = idx >> 3, c4 = idx & 7;
            const float4 va = *(const float4*)(Ag + (size_t)r * 768 + c4 * 4);
            uint4 ua;
            ua.x = f2tf32(va.x); ua.y = f2tf32(va.y);
            ua.z = f2tf32(va.z); ua.w = f2tf32(va.w);
            *(uint4*)(sA + r * 36 + c4 * 4) = ua;
            const float4 vb = *(const float4*)(Bg + (size_t)r * ldw + c4 * 4);
            uint4 ub;
            ub.x = f2tf32(vb.x); ub.y = f2tf32(vb.y);
            ub.z = f2tf32(vb.z); ub.w = f2tf32(vb.w);
            *(uint4*)(sB + r * 36 + c4 * 4) = ub;
        }
        __syncthreads();

#pragma unroll
        for (int kk = 0; kk < 32; kk += 8) {
            uint32_t a[2][4];
#pragma unroll
            for (int mt = 0; mt < 2; ++mt) {
                const int mb = mw * 32 + mt * 16;
                a[mt][0] = sA[(mb + g)     * 36 + kk + t];
                a[mt][1] = sA[(mb + g + 8) * 36 + kk + t];
                a[mt][2] = sA[(mb + g)     * 36 + kk + t + 4];
                a[mt][3] = sA[(mb + g + 8) * 36 + kk + t + 4];
            }
            uint32_t b[8][2];
#pragma unroll
            for (int nt = 0; nt < 8; ++nt) {
                const int cn = nw * 64 + nt * 8 + g;
                b[nt][0] = sB[cn * 36 + kk + t];
                b[nt][1] = sB[cn * 36 + kk + t + 4];
            }
#pragma unroll
            for (int mt = 0; mt < 2; ++mt)
#pragma unroll
                for (int nt = 0; nt < 8; ++nt)
                    mma_tf32(acc[mt][nt], a[mt], b[nt]);
        }
    }

#pragma unroll
    for (int mt = 0; mt < 2; ++mt) {
        const int r0 = m0 + mw * 32 + mt * 16 + g;
#pragma unroll
        for (int nt = 0; nt < 8; ++nt) {
            const int col = n0 + nw * 64 + nt * 8 + 2 * t;
            const float b0 = bias[col], b1 = bias[col + 1];
            float2 o0, o1;
            o0.x = fmaxf(acc[mt][nt][0] + b0, 0.f);
            o0.y = fmaxf(acc[mt][nt][1] + b1, 0.f);
            o1.x = fmaxf(acc[mt][nt][2] + b0, 0.f);
            o1.y = fmaxf(acc[mt][nt][3] + b1, 0.f);
            *(float2*)(C + (size_t)r0 * 768 + col)       = o0;
            *(float2*)(C + (size_t)(r0 + 8) * 768 + col) = o1;
        }
    }
}

// ---------------- launch ------------------------------------------------------
extern "C" void kernel_launch(void* const* d_in, const int* in_sizes, int n_in,
                              void* d_out, int out_size)
{
    const float* x    = (const float*)d_in[0];
    const int*   mask = (const int*)  d_in[1];
    const float* pos  = (const float*)d_in[2];
    const float* Wq   = (const float*)d_in[3];
    const float* bq   = (const float*)d_in[4];
    const float* Wk   = (const float*)d_in[5];
    const float* bk   = (const float*)d_in[6];
    const float* Wpam = (const float*)d_in[7];
    const float* bpam = (const float*)d_in[8];
    const float* Wm   = (const float*)d_in[9];
    const float* bm   = (const float*)d_in[10];
    float* out = (float*)d_out;

    float *gq, *gk, *gatt, *gpam, *gposp, *gwpt, *gwmt;
    cudaGetSymbolAddress((void**)&gq,    g_q);
    cudaGetSymbolAddress((void**)&gk,    g_k);
    cudaGetSymbolAddress((void**)&gatt,  g_att);
    cudaGetSymbolAddress((void**)&gpam,  g_pam);
    cudaGetSymbolAddress((void**)&gposp, g_posp);
    cudaGetSymbolAddress((void**)&gwpt,  g_wpt);
    cudaGetSymbolAddress((void**)&gwmt,  g_wmt);

    const int smem8   = flash_smem_bytes(8);
    const int smem192 = flash_smem_bytes(192);
    cudaFuncSetAttribute(flash_mma<8>,   cudaFuncAttributeMaxDynamicSharedMemorySize, smem8);
    cudaFuncSetAttribute(flash_mma<192>, cudaFuncAttributeMaxDynamicSharedMemorySize, smem192);

    const float sc_sam = 1.f / powf(8.f,   0.25f);
    const float sc_pam = 1.f / powf(192.f, 0.25f);

    // 0) transpose weights to K-major (mma row.col wants B k-contiguous)
    transpose_k<<<dim3(24, 24), 256>>>(Wpam, gwpt, 768, 768);
    transpose_k<<<dim3(24, 48), 256>>>(Wm,   gwmt, 1536, 768);

    // 1) q/k projections (+ReLU)
    qk_proj<<<1024, 256>>>(x, Wq, bq, Wk, bk, gq, gk);

    // 2) SAM attention (transposed-flash trick: Qflash = k, Kflash = q)
    flash_mma<8><<<dim3(16, NH, NB), 256, smem8>>>(gk, gq, 32, x, mask, gatt, sc_sam);

    // 3) PAM attention: Q = K = position
    flash_mma<192><<<dim3(16, NH, NB), 256, smem192>>>(pos, pos, DMODEL, x, mask, gpam, sc_pam);

    // 4) pos_proj = relu(pam_out @ Wpam + bpam)   [mma.sync tf32]
    gemm_mma<<<dim3(6, 64), 256>>>(gpam, nullptr, gwpt, 768, 24, bpam, gposp);

    // 5) out = relu(att @ Wm_top + pos_proj @ Wm_bot + bm)   [mma.sync tf32]
    gemm_mma<<<dim3(6, 64), 256>>>(gatt, gposp, gwmt, 1536, 48, bm, out);
}

// round 11
// speedup vs baseline: 3.4512x; 1.6545x over previous
#include <cuda_runtime.h>
#include <cuda_fp16.h>
#include <math.h>
#include <stdint.h>

#define BS   8192           // B*S
#define SEQ  1024
#define NB   8
#define NH   4
#define DMODEL 768
#define DV   192            // per-head V dim

// ---------------- scratch (static device memory; no allocations) -------------
__device__ __half   g_qh[BS * 32];
__device__ __half   g_kh[BS * 32];
__device__ float    g_posr[BS * DMODEL];              // tf32-rounded position
__device__ uint32_t g_vt[NB * NH * 192 * 512];        // V^T half2: [bh][d][i/2]
__device__ float    g_att[BS * DMODEL];
__device__ float    g_pam[BS * DMODEL];
__device__ float    g_posp[BS * DMODEL];
__device__ float    g_wpt[DMODEL * DMODEL];           // Wpam^T (tf32-rounded)
__device__ float    g_wmt[DMODEL * 2 * DMODEL];       // Wm^T   (tf32-rounded)

// ---------------- helpers ----------------------------------------------------
__device__ __forceinline__ uint32_t smem_u32(const void* p) {
    uint32_t a;
    asm("{ .reg .u64 t; cvta.to.shared.u64 t, %1; cvt.u32.u64 %0, t; }"
        : "=r"(a) : "l"(p));
    return a;
}
__device__ __forceinline__ float rna(float f) {
    uint32_t r;
    asm("cvt.rna.tf32.f32 %0, %1;" : "=r"(r) : "f"(f));
    return __uint_as_float(r);
}
__device__ __forceinline__ void mma_tf32(float c[4], const uint32_t a[4],
                                         const uint32_t b[2]) {
    asm volatile("mma.sync.aligned.m16n8k8.row.col.f32.tf32.tf32.f32 "
                 "{%0,%1,%2,%3}, {%4,%5,%6,%7}, {%8,%9}, {%0,%1,%2,%3};"
                 : "+f"(c[0]), "+f"(c[1]), "+f"(c[2]), "+f"(c[3])
                 : "r"(a[0]), "r"(a[1]), "r"(a[2]), "r"(a[3]),
                   "r"(b[0]), "r"(b[1]));
}
__device__ __forceinline__ void mma_f16(float c[4],
                                        uint32_t a0, uint32_t a1,
                                        uint32_t a2, uint32_t a3,
                                        uint32_t b0, uint32_t b1) {
    asm volatile("mma.sync.aligned.m16n8k16.row.col.f32.f16.f16.f32 "
                 "{%0,%1,%2,%3}, {%4,%5,%6,%7}, {%8,%9}, {%0,%1,%2,%3};"
                 : "+f"(c[0]), "+f"(c[1]), "+f"(c[2]), "+f"(c[3])
                 : "r"(a0), "r"(a1), "r"(a2), "r"(a3), "r"(b0), "r"(b1));
}
__device__ __forceinline__ uint32_t pack2h(float a, float b) {
    __half ha = __float2half_rn(a), hb = __float2half_rn(b);
    return (uint32_t)__half_as_ushort(ha) | ((uint32_t)__half_as_ushort(hb) << 16);
}
#define CP_ASYNC16(saddr, gptr) \
    asm volatile("cp.async.cg.shared.global [%0], [%1], 16;" \
                 :: "r"(saddr), "l"(gptr))
#define CP_ASYNC4(saddr, gptr) \
    asm volatile("cp.async.ca.shared.global [%0], [%1], 4;" \
                 :: "r"(saddr), "l"(gptr))
#define CP_COMMIT() asm volatile("cp.async.commit_group;")
#define CP_WAIT0()  asm volatile("cp.async.wait_group 0;")
#define CP_WAIT1()  asm volatile("cp.async.wait_group 1;")

// ---------------- prep kernels ------------------------------------------------
__global__ __launch_bounds__(256)
void prep_pos(const float* __restrict__ pos, float* __restrict__ out)
{
    const int idx = blockIdx.x * 256 + threadIdx.x;
    const float4 v = *(const float4*)(pos + (size_t)idx * 4);
    float4 o;
    o.x = rna(v.x); o.y = rna(v.y); o.z = rna(v.z); o.w = rna(v.w);
    *(float4*)(out + (size_t)idx * 4) = o;
}

// V^T prep: g_vt[(b*NH+h)*192+d][m] = half2(x[b][2m][h*192+d], x[b][2m+1][..])
__global__ __launch_bounds__(256)
void prep_vt(const float* __restrict__ x, uint32_t* __restrict__ vt)
{
    __shared__ float t[64][33];
    const int s0 = blockIdx.x * 64, c0 = blockIdx.y * 32, b = blockIdx.z;
    const int tid = threadIdx.x;
#pragma unroll
    for (int i = 0; i < 8; ++i) {
        const int idx = tid + i * 256;
        const int r = idx >> 5, cc = idx & 31;
        t[r][cc] = x[((size_t)b * SEQ + s0 + r) * DMODEL + c0 + cc];
    }
    __syncthreads();
#pragma unroll
    for (int i = 0; i < 4; ++i) {
        const int idx = tid + i * 256;
        const int cc = idx >> 5, m = idx & 31;
        const int c = c0 + cc, h = c / 192, d = c % 192;
        vt[((size_t)(b * NH + h) * 192 + d) * 512 + s0 / 2 + m]
            = pack2h(t[2 * m][cc], t[2 * m + 1][cc]);
    }
}

// weight transpose W[K][N] -> WT[N][K], tf32-rounded
__global__ __launch_bounds__(256)
void transpose_k(const float* __restrict__ W, float* __restrict__ WT, int K, int N)
{
    __shared__ float t[32][33];
    const int k0 = blockIdx.y * 32, n0 = blockIdx.x * 32;
    const int tx = threadIdx.x & 31, ty = threadIdx.x >> 5;
#pragma unroll
    for (int r = ty; r < 32; r += 8)
        t[r][tx] = W[(size_t)(k0 + r) * N + n0 + tx];
    __syncthreads();
#pragma unroll
    for (int r = ty; r < 32; r += 8)
        WT[(size_t)(n0 + r) * K + k0 + tx] = rna(t[tx][r]);
}

// ---------------- q/k projection + ReLU -> fp16 -------------------------------
__global__ __launch_bounds__(256)
void qk_proj(const float* __restrict__ x,
             const float* __restrict__ Wq, const float* __restrict__ bq,
             const float* __restrict__ Wk, const float* __restrict__ bk,
             __half* __restrict__ q, __half* __restrict__ k)
{
    const int row  = (blockIdx.x * blockDim.x + threadIdx.x) >> 5;
    const int lane = threadIdx.x & 31;
    if (row >= BS) return;
    const float* xr = x + (size_t)row * DMODEL;
    float aq = bq[lane];
    float ak = bk[lane];
#pragma unroll 8
    for (int d = 0; d < DMODEL; ++d) {
        const float xv = __ldg(xr + d);
        aq = fmaf(xv, __ldg(Wq + d * 32 + lane), aq);
        ak = fmaf(xv, __ldg(Wk + d * 32 + lane), ak);
    }
    q[(size_t)row * 32 + lane] = __float2half_rn(fmaxf(aq, 0.f));
    k[(size_t)row * 32 + lane] = __float2half_rn(fmaxf(ak, 0.f));
}

// ---------------- flash attention, cp.async pipelined --------------------------
// out[j] = sum_i softmax_i( Q[j]·K[i]*scale, masked ) * V[i]   (transpose trick)
// PAM=true : Q/K = tf32 fp32 rows of 192 (g_posr); QK^T via m16n8k8 tf32.
// PAM=false: Q/K = fp16 rows of 8 (g_kh/g_qh);    QK^T via one m16n8k16 fp16.
// PV: fp16 m16n8k16 from pre-transposed g_vt. 3 barriers/iter, double-buffered.
template<bool PAM>
__global__ __launch_bounds__(256)
void flash2(const float* __restrict__ Qf, const float* __restrict__ Kf,
            const __half* __restrict__ Qh, const __half* __restrict__ Kh,
            const uint32_t* __restrict__ Vt, const int* __restrict__ mask,
            float* __restrict__ Og, float scale)
{
    constexpr int LDK = PAM ? 196 : 12;       // u32 row stride (=4 mod 32)
    constexpr int OQ  = 0;
    constexpr int OK0 = OQ  + 64 * LDK;
    constexpr int OK1 = OK0 + 64 * LDK;
    constexpr int OV0 = OK1 + 64 * LDK;
    constexpr int OV1 = OV0 + 192 * 36;
    constexpr int OP  = OV1 + 192 * 36;
    constexpr int ORM = OP  + 64 * 36;
    constexpr int ORS = ORM + 128;
    constexpr int OMX = ORS + 128;            // [2][64]
    constexpr int OLX = OMX + 128;            // [2][64]
    constexpr int OMI = OLX + 128;            // [2][64] int

    extern __shared__ __align__(16) uint32_t sm[];
    float* fsm = (float*)sm;
    int*   ism = (int*)sm;
    const uint32_t sb = smem_u32(sm);

    const int tid = threadIdx.x;
    const int wid = tid >> 5, lane = tid & 31;
    const int g = lane >> 2, t = lane & 3;
    const int mw = wid >> 1, nw = wid & 1;
    const int r0 = mw * 16 + g, r1 = r0 + 8;
    const int qt = blockIdx.x, h = blockIdx.y, b = blockIdx.z;
    const int j0 = qt * 64;
    const long brow = (long)b * SEQ;
    const int bh = b * NH + h;

    // --- issue Q tile loads ---
    if (PAM) {
#pragma unroll
        for (int i = 0; i < 12; ++i) {
            const int idx = tid + i * 256;
            const int r = idx / 48, c = idx % 48;
            CP_ASYNC16(sb + (OQ + r * 196 + c * 4) * 4,
                       Qf + (brow + j0 + r) * (size_t)DMODEL + h * 192 + c * 4);
        }
    } else {
        if (tid < 64)
            CP_ASYNC16(sb + (OQ + tid * 12) * 4,
                       Qh + (brow + j0 + tid) * (size_t)32 + h * 8);
        // zero pad cols 4..7 of Q, K0, K1 (fp16 k16 upper half)
#pragma unroll
        for (int i = 0; i < 3; ++i) {
            const int idx = tid + i * 256;
            const int arr = idx >> 8, rem = idx & 255;
            const int r = rem >> 2, c = 4 + (rem & 3);
            const int base = (arr == 0) ? OQ : ((arr == 1) ? OK0 : OK1);
            sm[base + r * 12 + c] = 0;
        }
    }
    // init running stats + query mask
    if (tid < 64) {
        fsm[OMX + tid] = -1e30f;
        fsm[OLX + tid] = 0.f;
    }
    const int mj0 = mask[brow + j0 + r0];
    const int mj1 = mask[brow + j0 + r1];

    auto load_tile = [&](int kt, int bufsel) {
        const int i0 = kt * 64;
        const int OK = bufsel ? OK1 : OK0, OV = bufsel ? OV1 : OV0;
        if (PAM) {
#pragma unroll
            for (int i = 0; i < 12; ++i) {
                const int idx = tid + i * 256;
                const int r = idx / 48, c = idx % 48;
                CP_ASYNC16(sb + (OK + r * 196 + c * 4) * 4,
                           Kf + (brow + i0 + r) * (size_t)DMODEL + h * 192 + c * 4);
            }
        } else {
            if (tid < 64)
                CP_ASYNC16(sb + (OK + tid * 12) * 4,
                           Kh + (brow + i0 + tid) * (size_t)32 + h * 8);
        }
#pragma unroll
        for (int i = 0; i < 6; ++i) {
            const int idx = tid + i * 256;
            const int r = idx >> 3, c = idx & 7;
            CP_ASYNC16(sb + (OV + r * 36 + c * 4) * 4,
                       Vt + ((size_t)bh * 192 + r) * 512 + kt * 32 + c * 4);
        }
        if (tid < 64)
            CP_ASYNC4(sb + (OMI + (kt & 1) * 64 + tid) * 4, mask + brow + i0 + tid);
    };
    load_tile(0, 0);
    CP_COMMIT();

    float acc[12][4];
#pragma unroll
    for (int n2 = 0; n2 < 12; ++n2)
#pragma unroll
        for (int e = 0; e < 4; ++e) acc[n2][e] = 0.f;

    for (int kt = 0; kt < 16; ++kt) {
        CP_WAIT0();
        __syncthreads();                              // (a) tile ready, prev PV done
        if (kt + 1 < 16) load_tile(kt + 1, (kt + 1) & 1);
        CP_COMMIT();
        const int OK = (kt & 1) ? OK1 : OK0;
        const int OV = (kt & 1) ? OV1 : OV0;

        // ---- S = Q K^T ----
        float s[4][4];
#pragma unroll
        for (int nt = 0; nt < 4; ++nt)
#pragma unroll
            for (int e = 0; e < 4; ++e) s[nt][e] = 0.f;
        if (PAM) {
#pragma unroll
            for (int ck = 0; ck < 24; ++ck) {
                uint32_t a[4];
                a[0] = sm[OQ + r0 * 196 + ck * 8 + t];
                a[1] = sm[OQ + r1 * 196 + ck * 8 + t];
                a[2] = sm[OQ + r0 * 196 + ck * 8 + t + 4];
                a[3] = sm[OQ + r1 * 196 + ck * 8 + t + 4];
#pragma unroll
                for (int nt = 0; nt < 4; ++nt) {
                    const int iw = nw * 32 + nt * 8 + g;
                    uint32_t bb[2];
                    bb[0] = sm[OK + iw * 196 + ck * 8 + t];
                    bb[1] = sm[OK + iw * 196 + ck * 8 + t + 4];
                    mma_tf32(s[nt], a, bb);
                }
            }
        } else {
            const uint32_t a0 = sm[OQ + r0 * 12 + t];
            const uint32_t a1 = sm[OQ + r1 * 12 + t];
            const uint32_t a2 = sm[OQ + r0 * 12 + t + 4];
            const uint32_t a3 = sm[OQ + r1 * 12 + t + 4];
#pragma unroll
            for (int nt = 0; nt < 4; ++nt) {
                const int iw = nw * 32 + nt * 8 + g;
                const uint32_t b0 = sm[OK + iw * 12 + t];
                const uint32_t b1 = sm[OK + iw * 12 + t + 4];
                mma_f16(s[nt], a0, a1, a2, a3, b0, b1);
            }
        }

        // ---- mask + scale + row max (warp-local over 32-i slice) ----
        const int obMI = OMI + (kt & 1) * 64;
        float vv[4][4];
        float m0 = -1e30f, m1 = -1e30f;
#pragma unroll
        for (int nt = 0; nt < 4; ++nt) {
            const int ii = nw * 32 + nt * 8 + 2 * t;
            const int mi0 = ism[obMI + ii], mi1 = ism[obMI + ii + 1];
            vv[nt][0] = (mj0 && mi0) ? s[nt][0] * scale : -1e7f;
            vv[nt][1] = (mj0 && mi1) ? s[nt][1] * scale : -1e7f;
            vv[nt][2] = (mj1 && mi0) ? s[nt][2] * scale : -1e7f;
            vv[nt][3] = (mj1 && mi1) ? s[nt][3] * scale : -1e7f;
            m0 = fmaxf(m0, fmaxf(vv[nt][0], vv[nt][1]));
            m1 = fmaxf(m1, fmaxf(vv[nt][2], vv[nt][3]));
        }
        m0 = fmaxf(m0, __shfl_xor_sync(0xffffffffu, m0, 1));
        m0 = fmaxf(m0, __shfl_xor_sync(0xffffffffu, m0, 2));
        m1 = fmaxf(m1, __shfl_xor_sync(0xffffffffu, m1, 1));
        m1 = fmaxf(m1, __shfl_xor_sync(0xffffffffu, m1, 2));
        if (t == 0) {
            fsm[ORM + nw * 64 + r0] = m0;
            fsm[ORM + nw * 64 + r1] = m1;
        }
        __syncthreads();                              // (b)

        // per-thread combine (no broadcast phase)
        const float mr0 = fmaxf(fsm[ORM + r0], fsm[ORM + 64 + r0]);
        const float mr1 = fmaxf(fsm[ORM + r1], fsm[ORM + 64 + r1]);
        const float mo0 = fsm[OMX + (kt & 1) * 64 + r0];
        const float mo1 = fsm[OMX + (kt & 1) * 64 + r1];
        const float mn0 = fmaxf(mo0, mr0), mn1 = fmaxf(mo1, mr1);
        const float c0f = __expf(mo0 - mn0), c1f = __expf(mo1 - mn1);
        if (nw == 0 && t == 0) {
            fsm[OMX + ((kt + 1) & 1) * 64 + r0] = mn0;
            fsm[OMX + ((kt + 1) & 1) * 64 + r1] = mn1;
        }

        // ---- exp, pack P, partial row sums ----
        float l0 = 0.f, l1 = 0.f;
#pragma unroll
        for (int nt = 0; nt < 4; ++nt) {
            const float p00 = __expf(vv[nt][0] - mn0);
            const float p01 = __expf(vv[nt][1] - mn0);
            const float p10 = __expf(vv[nt][2] - mn1);
            const float p11 = __expf(vv[nt][3] - mn1);
            l0 += p00 + p01;
            l1 += p10 + p11;
            sm[OP + r0 * 36 + nw * 16 + nt * 4 + t] = pack2h(p00, p01);
            sm[OP + r1 * 36 + nw * 16 + nt * 4 + t] = pack2h(p10, p11);
        }
        l0 += __shfl_xor_sync(0xffffffffu, l0, 1);
        l0 += __shfl_xor_sync(0xffffffffu, l0, 2);
        l1 += __shfl_xor_sync(0xffffffffu, l1, 1);
        l1 += __shfl_xor_sync(0xffffffffu, l1, 2);
        if (t == 0) {
            fsm[ORS + nw * 64 + r0] = l0;
            fsm[ORS + nw * 64 + r1] = l1;
        }
        __syncthreads();                              // (c)
        if (nw == 0 && t == 0) {
            fsm[OLX + ((kt + 1) & 1) * 64 + r0]
                = fsm[OLX + (kt & 1) * 64 + r0] * c0f + fsm[ORS + r0] + fsm[ORS + 64 + r0];
            fsm[OLX + ((kt + 1) & 1) * 64 + r1]
                = fsm[OLX + (kt & 1) * 64 + r1] * c1f + fsm[ORS + r1] + fsm[ORS + 64 + r1];
        }

        // ---- O = O*corr + P V ----
#pragma unroll
        for (int n2 = 0; n2 < 12; ++n2) {
            acc[n2][0] *= c0f; acc[n2][1] *= c0f;
            acc[n2][2] *= c1f; acc[n2][3] *= c1f;
        }
#pragma unroll
        for (int ck = 0; ck < 4; ++ck) {
            const uint32_t pa0 = sm[OP + r0 * 36 + ck * 8 + t];
            const uint32_t pa1 = sm[OP + r1 * 36 + ck * 8 + t];
            const uint32_t pa2 = sm[OP + r0 * 36 + ck * 8 + t + 4];
            const uint32_t pa3 = sm[OP + r1 * 36 + ck * 8 + t + 4];
#pragma unroll
            for (int n2 = 0; n2 < 12; ++n2) {
                const int d0 = nw * 96 + n2 * 8 + g;
                const uint32_t b0 = sm[OV + d0 * 36 + ck * 8 + t];
                const uint32_t b1 = sm[OV + d0 * 36 + ck * 8 + t + 4];
                mma_f16(acc[n2], pa0, pa1, pa2, pa3, b0, b1);
            }
        }
    }
    __syncthreads();   // final LX visible

    const float inv0 = 1.f / fsm[OLX + r0];   // parity (15+1)&1 == 0
    const float inv1 = 1.f / fsm[OLX + r1];
#pragma unroll
    for (int n2 = 0; n2 < 12; ++n2) {
        const int col = nw * 96 + n2 * 8 + 2 * t;
        float2 o0, o1;
        o0.x = rna(acc[n2][0] * inv0); o0.y = rna(acc[n2][1] * inv0);
        o1.x = rna(acc[n2][2] * inv1); o1.y = rna(acc[n2][3] * inv1);
        *(float2*)(Og + (brow + j0 + r0) * (size_t)DMODEL + h * DV + col) = o0;
        *(float2*)(Og + (brow + j0 + r1) * (size_t)DMODEL + h * DV + col) = o1;
    }
}

static int flash_smem_bytes(bool pam) {
    const int ldk = pam ? 196 : 12;
    const int u = 64 * ldk * 3 + 192 * 36 * 2 + 64 * 36 + 128 * 5;
    return u * 4;
}

// ---------------- tf32 GEMM, cp.async double-buffered + bias + ReLU ----------
// C[m][n] = relu( sum_k A(k)[m][k] * WT[n][k] + bias[n] ); operands pre-rounded.
__global__ __launch_bounds__(256, 2)
void gemm_cp(const float* __restrict__ A0, const float* __restrict__ A1,
             const float* __restrict__ WT, int ldw, int nk,
             const float* __restrict__ bias, float* __restrict__ C,
             int round_out)
{
    extern __shared__ __align__(16) uint32_t gsm[];   // sA[2][4608] sB[2][4608]
    const uint32_t sbase = smem_u32(gsm);

    const int tid  = threadIdx.x;
    const int wid  = tid >> 5, lane = tid & 31;
    const int g    = lane >> 2, t = lane & 3;
    const int mw   = wid >> 1;
    const int nw   = wid & 1;
    const int n0   = blockIdx.x * 128;
    const int m0   = blockIdx.y * 128;

    auto issue = [&](int kc, int st) {
        const int kb = kc * 32;
        const float* Ag = (kb < 768) ? (A0 + (size_t)m0 * 768 + kb)
                                     : (A1 + (size_t)m0 * 768 + (kb - 768));
        const float* Bg = WT + (size_t)n0 * ldw + kb;
#pragma unroll
        for (int i = 0; i < 4; ++i) {
            const int idx = tid + i * 256;
            const int r = idx >> 3, c = idx & 7;
            CP_ASYNC16(sbase + (st * 4608 + r * 36 + c * 4) * 4,
                       Ag + (size_t)r * 768 + c * 4);
            CP_ASYNC16(sbase + (9216 + st * 4608 + r * 36 + c * 4) * 4,
                       Bg + (size_t)r * ldw + c * 4);
        }
    };

    float acc[2][8][4];
#pragma unroll
    for (int mt = 0; mt < 2; ++mt)
#pragma unroll
        for (int nt = 0; nt < 8; ++nt)
#pragma unroll
            for (int e = 0; e < 4; ++e) acc[mt][nt][e] = 0.f;

    issue(0, 0);
    CP_COMMIT();

    for (int kc = 0; kc < nk; ++kc) {
        if (kc + 1 < nk) {
            issue(kc + 1, (kc + 1) & 1);
            CP_COMMIT();
            CP_WAIT1();
        } else {
            CP_WAIT0();
        }
        __syncthreads();

        const uint32_t* sA = gsm + (kc & 1) * 4608;
        const uint32_t* sB = gsm + 9216 + (kc & 1) * 4608;
#pragma unroll
        for (int kk = 0; kk < 32; kk += 8) {
            uint32_t a[2][4];
#pragma unroll
            for (int mt = 0; mt < 2; ++mt) {
                const int mb = mw * 32 + mt * 16;
                a[mt][0] = sA[(mb + g)     * 36 + kk + t];
                a[mt][1] = sA[(mb + g + 8) * 36 + kk + t];
                a[mt][2] = sA[(mb + g)     * 36 + kk + t + 4];
                a[mt][3] = sA[(mb + g + 8) * 36 + kk + t + 4];
            }
            uint32_t b[8][2];
#pragma unroll
            for (int nt = 0; nt < 8; ++nt) {
                const int cn = nw * 64 + nt * 8 + g;
                b[nt][0] = sB[cn * 36 + kk + t];
                b[nt][1] = sB[cn * 36 + kk + t + 4];
            }
#pragma unroll
            for (int mt = 0; mt < 2; ++mt)
#pragma unroll
                for (int nt = 0; nt < 8; ++nt)
                    mma_tf32(acc[mt][nt], a[mt], b[nt]);
        }
        __syncthreads();
    }

#pragma unroll
    for (int mt = 0; mt < 2; ++mt) {
        const int r0 = m0 + mw * 32 + mt * 16 + g;
#pragma unroll
        for (int nt = 0; nt < 8; ++nt) {
            const int col = n0 + nw * 64 + nt * 8 + 2 * t;
            const float b0 = __ldg(bias + col), b1 = __ldg(bias + col + 1);
            float2 o0, o1;
            o0.x = fmaxf(acc[mt][nt][0] + b0, 0.f);
            o0.y = fmaxf(acc[mt][nt][1] + b1, 0.f);
            o1.x = fmaxf(acc[mt][nt][2] + b0, 0.f);
            o1.y = fmaxf(acc[mt][nt][3] + b1, 0.f);
            if (round_out) {
                o0.x = rna(o0.x); o0.y = rna(o0.y);
                o1.x = rna(o1.x); o1.y = rna(o1.y);
            }
            *(float2*)(C + (size_t)r0 * 768 + col)       = o0;
            *(float2*)(C + (size_t)(r0 + 8) * 768 + col) = o1;
        }
    }
}

// ---------------- launch ------------------------------------------------------
extern "C" void kernel_launch(void* const* d_in, const int* in_sizes, int n_in,
                              void* d_out, int out_size)
{
    const float* x    = (const float*)d_in[0];
    const int*   mask = (const int*)  d_in[1];
    const float* pos  = (const float*)d_in[2];
    const float* Wq   = (const float*)d_in[3];
    const float* bq   = (const float*)d_in[4];
    const float* Wk   = (const float*)d_in[5];
    const float* bk   = (const float*)d_in[6];
    const float* Wpam = (const float*)d_in[7];
    const float* bpam = (const float*)d_in[8];
    const float* Wm   = (const float*)d_in[9];
    const float* bm   = (const float*)d_in[10];
    float* out = (float*)d_out;

    __half *gqh, *gkh;
    float *gposr, *gatt, *gpam, *gposp, *gwpt, *gwmt;
    uint32_t* gvt;
    cudaGetSymbolAddress((void**)&gqh,   g_qh);
    cudaGetSymbolAddress((void**)&gkh,   g_kh);
    cudaGetSymbolAddress((void**)&gposr, g_posr);
    cudaGetSymbolAddress((void**)&gvt,   g_vt);
    cudaGetSymbolAddress((void**)&gatt,  g_att);
    cudaGetSymbolAddress((void**)&gpam,  g_pam);
    cudaGetSymbolAddress((void**)&gposp, g_posp);
    cudaGetSymbolAddress((void**)&gwpt,  g_wpt);
    cudaGetSymbolAddress((void**)&gwmt,  g_wmt);

    const int smem_sam = flash_smem_bytes(false);   //  76,288 B
    const int smem_pam = flash_smem_bytes(true);    // 217,600 B
    const int smem_gemm = 18432 * 4;                //  73,728 B
    cudaFuncSetAttribute(flash2<false>, cudaFuncAttributeMaxDynamicSharedMemorySize, smem_sam);
    cudaFuncSetAttribute(flash2<true>,  cudaFuncAttributeMaxDynamicSharedMemorySize, smem_pam);
    cudaFuncSetAttribute(gemm_cp,       cudaFuncAttributeMaxDynamicSharedMemorySize, smem_gemm);

    const float sc_sam = 1.f / powf(8.f,   0.25f);
    const float sc_pam = 1.f / powf(192.f, 0.25f);

    // 0) operand prep
    prep_pos<<<BS * DMODEL / 1024, 256>>>(pos, gposr);
    prep_vt<<<dim3(16, 24, NB), 256>>>(x, gvt);
    transpose_k<<<dim3(24, 24), 256>>>(Wpam, gwpt, 768, 768);
    transpose_k<<<dim3(24, 48), 256>>>(Wm,   gwmt, 1536, 768);

    // 1) q/k projections (+ReLU) -> fp16
    qk_proj<<<1024, 256>>>(x, Wq, bq, Wk, bk, gqh, gkh);

    // 2) SAM attention (transposed-flash: Qflash = k, Kflash = q)
    flash2<false><<<dim3(16, NH, NB), 256, smem_sam>>>(
        nullptr, nullptr, gkh, gqh, gvt, mask, gatt, sc_sam);

    // 3) PAM attention: Q = K = position (tf32 QK^T)
    flash2<true><<<dim3(16, NH, NB), 256, smem_pam>>>(
        gposr, gposr, nullptr, nullptr, gvt, mask, gpam, sc_pam);

    // 4) pos_proj = relu(pam_out @ Wpam + bpam)
    gemm_cp<<<dim3(6, 64), 256, smem_gemm>>>(gpam, nullptr, gwpt, 768, 24, bpam, gposp, 1);

    // 5) out = relu(att @ Wm_top + pos_proj @ Wm_bot + bm)
    gemm_cp<<<dim3(6, 64), 256, smem_gemm>>>(gatt, gposp, gwmt, 1536, 48, bm, out, 0);
}